// round 5
// baseline (speedup 1.0000x reference)
#include <cuda_runtime.h>

#define NB 16
#define ND 64
#define NN 200
#define NT 48
#define NH 8

// intermediate h = x^T + LN(temporal_out):  (B,N,T,D)
__device__ float g_h[NB * NN * NT * ND];

// ---------------------------------------------------------------------------
// Kernel 1: per (b, n). conv1x3 q/k, linear v, 8-head attention over T=48,
// W2 projection, LayerNorm + residual -> g_h.
// smem floats: xs[64][50]@0, wbuf[6240]@3200, qs[64][52]@9440, ks[64][52]@12768,
//              vs[48][65]@16096, ss[48][52]@19216, aos[48][65]@21712,
//              ys[48][65]@24832  => 27952 floats = 111808 B
// ---------------------------------------------------------------------------
__global__ void __launch_bounds__(256, 2) temporal_kernel(
    const float* __restrict__ x,
    const float* __restrict__ Wq, const float* __restrict__ bq,
    const float* __restrict__ Wk, const float* __restrict__ bk,
    const float* __restrict__ W1, const float* __restrict__ b1,
    const float* __restrict__ W2, const float* __restrict__ b2,
    const float* __restrict__ g0, const float* __restrict__ beta0)
{
    extern __shared__ float sm[];
    float* xs   = sm;
    float* wbuf = sm + 3200;
    float* qs   = sm + 9440;
    float* ks   = sm + 12768;
    float* vs   = sm + 16096;
    float* ss   = sm + 19216;
    float* aos  = sm + 21712;
    float* ys   = sm + 24832;

    const int n   = blockIdx.x;
    const int b   = blockIdx.y;
    const int tid = threadIdx.x;
    const int d   = tid & 63;
    const int t0  = (tid >> 6) * 12;
    const int lane = tid & 31;
    const int warp = tid >> 5;

    // load x tile: x[b][e][n][t] -> xs[e][1+t], zero pad cols 0 and 49
    const float* xbase = x + ((long)(b * 64) * 200 + n) * 48;
    for (int i = tid; i < 64 * 48; i += 256) {
        int e = i / 48, t = i % 48;
        xs[e * 50 + 1 + t] = xbase[(long)e * 9600 + t];
    }
    if (tid < 128) {
        int e = tid & 63;
        xs[e * 50 + ((tid < 64) ? 0 : 49)] = 0.f;
    }

    // conv1x3 q/k as GEMM over (e,k); weights staged transposed in 16-e chunks
    float qa[12], ka[12];
    #pragma unroll
    for (int j = 0; j < 12; j++) { qa[j] = 0.f; ka[j] = 0.f; }

    for (int c = 0; c < 4; c++) {
        const int e0 = c * 16;
        __syncthreads();
        for (int i = tid; i < 64 * 48; i += 256) {
            int dd = i / 48, r = i % 48;
            wbuf[r * 65 + dd]        = Wq[dd * 192 + e0 * 3 + r];
            wbuf[3120 + r * 65 + dd] = Wk[dd * 192 + e0 * 3 + r];
        }
        __syncthreads();
        #pragma unroll
        for (int el = 0; el < 16; el++) {
            const float* xr = xs + (e0 + el) * 50 + t0;  // xr[j] = x[e][t0-1+j]
            float xv[14];
            #pragma unroll
            for (int j = 0; j < 14; j++) xv[j] = xr[j];
            float wq0 = wbuf[(el * 3 + 0) * 65 + d];
            float wq1 = wbuf[(el * 3 + 1) * 65 + d];
            float wq2 = wbuf[(el * 3 + 2) * 65 + d];
            float wk0 = wbuf[3120 + (el * 3 + 0) * 65 + d];
            float wk1 = wbuf[3120 + (el * 3 + 1) * 65 + d];
            float wk2 = wbuf[3120 + (el * 3 + 2) * 65 + d];
            #pragma unroll
            for (int j = 0; j < 12; j++) {
                qa[j] += wq0 * xv[j] + wq1 * xv[j + 1] + wq2 * xv[j + 2];
                ka[j] += wk0 * xv[j] + wk1 * xv[j + 1] + wk2 * xv[j + 2];
            }
        }
    }
    {
        float bqv = __ldg(bq + d), bkv = __ldg(bk + d);
        #pragma unroll
        for (int j = 0; j < 12; j++) {
            qs[d * 52 + t0 + j] = qa[j] + bqv;
            ks[d * 52 + t0 + j] = ka[j] + bkv;
        }
    }

    // v = x^T @ W1^T + b1
    __syncthreads();
    for (int i = tid; i < 4096; i += 256)
        wbuf[(i & 63) * 65 + (i >> 6)] = W1[i];   // wbuf[e*65+d] = W1[d][e]
    __syncthreads();
    {
        float va[12];
        float b1v = __ldg(b1 + d);
        #pragma unroll
        for (int j = 0; j < 12; j++) va[j] = b1v;
        for (int e = 0; e < 64; e++) {
            float w = wbuf[e * 65 + d];
            const float* xr = xs + e * 50 + 1 + t0;
            #pragma unroll
            for (int j = 0; j < 12; j++) va[j] += w * xr[j];
        }
        #pragma unroll
        for (int j = 0; j < 12; j++) vs[(t0 + j) * 65 + d] = va[j];
    }
    __syncthreads();

    // attention, one head at a time
    const float scale = 0.35355339059327373f; // 1/sqrt(8)
    for (int h = 0; h < NH; h++) {
        for (int w = tid; w < 576; w += 256) {
            int t = w / 12, u0 = (w % 12) * 4;
            float4 acc = make_float4(0.f, 0.f, 0.f, 0.f);
            #pragma unroll
            for (int dk = 0; dk < 8; dk++) {
                int dd = h * 8 + dk;
                float  qv = qs[dd * 52 + t];
                float4 kv = *(const float4*)(ks + dd * 52 + u0);
                acc.x += qv * kv.x; acc.y += qv * kv.y;
                acc.z += qv * kv.z; acc.w += qv * kv.w;
            }
            acc.x *= scale; acc.y *= scale; acc.z *= scale; acc.w *= scale;
            *(float4*)(ss + t * 52 + u0) = acc;
        }
        __syncthreads();
        for (int t = warp; t < 48; t += 8) {
            float s1 = ss[t * 52 + lane];
            float s2 = (lane < 16) ? ss[t * 52 + lane + 32] : -1e30f;
            float mx = fmaxf(s1, s2);
            #pragma unroll
            for (int o = 16; o > 0; o >>= 1) mx = fmaxf(mx, __shfl_xor_sync(0xffffffffu, mx, o));
            float e1 = __expf(s1 - mx);
            float e2 = (lane < 16) ? __expf(s2 - mx) : 0.f;
            float sum = e1 + e2;
            #pragma unroll
            for (int o = 16; o > 0; o >>= 1) sum += __shfl_xor_sync(0xffffffffu, sum, o);
            float inv = 1.f / sum;
            ss[t * 52 + lane] = e1 * inv;
            if (lane < 16) ss[t * 52 + lane + 32] = e2 * inv;
        }
        __syncthreads();
        for (int w = tid; w < 384; w += 256) {
            int t = w >> 3, dk = w & 7, dd = h * 8 + dk;
            float acc = 0.f;
            #pragma unroll
            for (int u0 = 0; u0 < 48; u0 += 4) {
                float4 p = *(const float4*)(ss + t * 52 + u0);
                acc += p.x * vs[(u0 + 0) * 65 + dd];
                acc += p.y * vs[(u0 + 1) * 65 + dd];
                acc += p.z * vs[(u0 + 2) * 65 + dd];
                acc += p.w * vs[(u0 + 3) * 65 + dd];
            }
            aos[t * 65 + dd] = acc;
        }
        __syncthreads();
    }

    // y = ao @ W2^T + b2
    for (int i = tid; i < 4096; i += 256)
        wbuf[(i & 63) * 65 + (i >> 6)] = W2[i];
    __syncthreads();
    {
        float ya[12];
        float b2v = __ldg(b2 + d);
        #pragma unroll
        for (int j = 0; j < 12; j++) ya[j] = b2v;
        for (int e = 0; e < 64; e++) {
            float w = wbuf[e * 65 + d];
            #pragma unroll
            for (int j = 0; j < 12; j++) ya[j] += w * aos[(t0 + j) * 65 + e];
        }
        #pragma unroll
        for (int j = 0; j < 12; j++) ys[(t0 + j) * 65 + d] = ya[j];
    }
    __syncthreads();

    // LayerNorm over d + residual x^T -> g_h
    float* hout = g_h + ((long)(b * 200 + n)) * 48 * 64;
    for (int t = warp; t < 48; t += 8) {
        float y1 = ys[t * 65 + lane];
        float y2 = ys[t * 65 + lane + 32];
        float s = y1 + y2;
        #pragma unroll
        for (int o = 16; o > 0; o >>= 1) s += __shfl_xor_sync(0xffffffffu, s, o);
        float mean = s * (1.f / 64.f);
        float d1 = y1 - mean, d2 = y2 - mean;
        float vv = d1 * d1 + d2 * d2;
        #pragma unroll
        for (int o = 16; o > 0; o >>= 1) vv += __shfl_xor_sync(0xffffffffu, vv, o);
        float rstd = rsqrtf(vv * (1.f / 64.f) + 1e-5f);
        float h1 = xs[lane * 50 + 1 + t]        + d1 * rstd * __ldg(g0 + lane)      + __ldg(beta0 + lane);
        float h2 = xs[(lane + 32) * 50 + 1 + t] + d2 * rstd * __ldg(g0 + lane + 32) + __ldg(beta0 + lane + 32);
        hout[t * 64 + lane]      = h1;
        hout[t * 64 + lane + 32] = h2;
    }
}

// ---------------------------------------------------------------------------
// Kernel 2: per (b, t). Flash-style spatial softmax-GCN over N=200, aggregate
// in registers (13x4/thread), Theta GEMM + relu, LayerNorm + residual -> out.
// smem floats: hs[200][65]@0, S[200][68]@13000, rmax@26600, rsum@26800,
//              fac@27000 => 27200 floats = 108800 B
// ---------------------------------------------------------------------------
template<int R0, int RN>
__device__ __forceinline__ void score_gemm_half(const float* __restrict__ hs,
                                                float* __restrict__ S,
                                                int ty, int tx, int m0)
{
    float sc[RN][4];
    #pragma unroll
    for (int r = 0; r < RN; r++)
        #pragma unroll
        for (int c = 0; c < 4; c++) sc[r][c] = 0.f;

    int nr[RN];
    #pragma unroll
    for (int r = 0; r < RN; r++) {
        int nn = ty + 16 * (R0 + r);
        nr[r] = (nn < 200) ? nn : 199;
    }
    int mc[4];
    #pragma unroll
    for (int c = 0; c < 4; c++) {
        int m = m0 + tx + 16 * c;
        mc[c] = (m < 200) ? m : 199;
    }
    for (int dd = 0; dd < 64; dd++) {
        float a[RN];
        #pragma unroll
        for (int r = 0; r < RN; r++) a[r] = hs[nr[r] * 65 + dd];
        float bb[4];
        #pragma unroll
        for (int c = 0; c < 4; c++) bb[c] = hs[mc[c] * 65 + dd];
        #pragma unroll
        for (int r = 0; r < RN; r++)
            #pragma unroll
            for (int c = 0; c < 4; c++) sc[r][c] += a[r] * bb[c];
    }
    #pragma unroll
    for (int r = 0; r < RN; r++) {
        int nn = ty + 16 * (R0 + r);
        if (nn < 200) {
            #pragma unroll
            for (int c = 0; c < 4; c++) {
                int m = m0 + tx + 16 * c;
                if (m < 200) S[nn * 68 + tx + 16 * c] = sc[r][c] * 0.125f;
            }
        }
    }
}

__global__ void __launch_bounds__(256, 2) spatial_kernel(
    const float* __restrict__ adj, const float* __restrict__ Theta,
    const float* __restrict__ g1,  const float* __restrict__ beta1,
    float* __restrict__ out)
{
    extern __shared__ float sm[];
    float* hs   = sm;            // [200][65]
    float* S    = sm + 13000;    // [200][68]; later Theta^T [64][68]
    float* rmax = sm + 26600;
    float* rsum = sm + 26800;
    float* fac  = sm + 27000;

    const int t = blockIdx.x, b = blockIdx.y;
    const int tid = threadIdx.x;
    const int tx = tid & 15, ty = tid >> 4;
    const int lane = tid & 31, warp = tid >> 5;

    const float* hbase = g_h + (long)b * 200 * 48 * 64 + (long)t * 64;
    for (int i = tid; i < 200 * 64; i += 256) {
        int nn = i >> 6, dd = i & 63;
        hs[nn * 65 + dd] = hbase[(long)nn * 3072 + dd];
    }
    for (int i = tid; i < 200; i += 256) { rmax[i] = -1e30f; rsum[i] = 0.f; }

    float agg[13][4];
    #pragma unroll
    for (int r = 0; r < 13; r++)
        #pragma unroll
        for (int c = 0; c < 4; c++) agg[r][c] = 0.f;

    __syncthreads();

    for (int ci = 0; ci < 4; ci++) {
        const int m0 = ci * 64;
        const int MC = (ci == 3) ? 8 : 64;

        score_gemm_half<0, 7>(hs, S, ty, tx, m0);
        score_gemm_half<7, 6>(hs, S, ty, tx, m0);
        __syncthreads();

        // online softmax update + adjacency weighting (warp per row)
        for (int nn = warp; nn < 200; nn += 8) {
            float s1 = (lane < MC)      ? S[nn * 68 + lane]      : -1e30f;
            float s2 = (lane + 32 < MC) ? S[nn * 68 + lane + 32] : -1e30f;
            float mx = fmaxf(s1, s2);
            #pragma unroll
            for (int o = 16; o > 0; o >>= 1) mx = fmaxf(mx, __shfl_xor_sync(0xffffffffu, mx, o));
            float rm = rmax[nn];
            float nm = fmaxf(rm, mx);
            float f  = __expf(rm - nm);
            float e1 = (lane < MC)      ? __expf(s1 - nm) : 0.f;
            float e2 = (lane + 32 < MC) ? __expf(s2 - nm) : 0.f;
            float cs = e1 + e2;
            #pragma unroll
            for (int o = 16; o > 0; o >>= 1) cs += __shfl_xor_sync(0xffffffffu, cs, o);
            if (lane == 0) { rsum[nn] = rsum[nn] * f + cs; rmax[nn] = nm; fac[nn] = f; }
            const float* arow = adj + (long)nn * 200 + m0;
            if (lane < MC)      S[nn * 68 + lane]      = e1 * __ldg(arow + lane);
            if (lane + 32 < MC) S[nn * 68 + lane + 32] = e2 * __ldg(arow + lane + 32);
        }
        __syncthreads();

        // agg = agg*fac + P_chunk @ h_chunk
        {
            float fr[13];
            #pragma unroll
            for (int r = 0; r < 13; r++) {
                int nn = ty + 16 * r;
                fr[r] = fac[(nn < 200) ? nn : 199];
            }
            #pragma unroll
            for (int r = 0; r < 13; r++)
                #pragma unroll
                for (int c = 0; c < 4; c++) agg[r][c] *= fr[r];

            for (int m = 0; m < MC; m++) {
                float w[13];
                #pragma unroll
                for (int r = 0; r < 13; r++) {
                    int nn = ty + 16 * r;
                    w[r] = S[((nn < 200) ? nn : 199) * 68 + m];
                }
                float hb[4];
                #pragma unroll
                for (int c = 0; c < 4; c++) hb[c] = hs[(m0 + m) * 65 + tx + 16 * c];
                #pragma unroll
                for (int r = 0; r < 13; r++)
                    #pragma unroll
                    for (int c = 0; c < 4; c++) agg[r][c] += w[r] * hb[c];
            }
        }
        __syncthreads();
    }

    // finalize: agg /= (rsum * sqrt(D))
    #pragma unroll
    for (int r = 0; r < 13; r++) {
        int nn = ty + 16 * r;
        float inv = 1.f / (rsum[(nn < 200) ? nn : 199] * 8.f);
        #pragma unroll
        for (int c = 0; c < 4; c++) agg[r][c] *= inv;
    }

    // overwrite hs with agg; stage Theta transposed into S
    #pragma unroll
    for (int r = 0; r < 13; r++) {
        int nn = ty + 16 * r;
        if (nn < 200) {
            #pragma unroll
            for (int c = 0; c < 4; c++) hs[nn * 65 + tx + 16 * c] = agg[r][c];
        }
    }
    for (int i = tid; i < 4096; i += 256)
        S[(i & 63) * 68 + (i >> 6)] = Theta[i];   // S[f*68+j] = Theta[j][f]
    __syncthreads();

    // G = relu(agg @ Theta^T)
    float g[13][4];
    #pragma unroll
    for (int r = 0; r < 13; r++)
        #pragma unroll
        for (int c = 0; c < 4; c++) g[r][c] = 0.f;
    {
        int nr[13];
        #pragma unroll
        for (int r = 0; r < 13; r++) {
            int nn = ty + 16 * r;
            nr[r] = (nn < 200) ? nn : 199;
        }
        for (int dd = 0; dd < 64; dd++) {
            float a[13];
            #pragma unroll
            for (int r = 0; r < 13; r++) a[r] = hs[nr[r] * 65 + dd];
            float bb[4];
            #pragma unroll
            for (int c = 0; c < 4; c++) bb[c] = S[dd * 68 + tx + 16 * c];
            #pragma unroll
            for (int r = 0; r < 13; r++)
                #pragma unroll
                for (int c = 0; c < 4; c++) g[r][c] += a[r] * bb[c];
        }
    }
    #pragma unroll
    for (int r = 0; r < 13; r++)
        #pragma unroll
        for (int c = 0; c < 4; c++) g[r][c] = fmaxf(g[r][c], 0.f);

    // LayerNorm over j (width-16 shuffles) + residual (h from gmem) + store
    float* obase = out + (long)b * 200 * 3072 + (long)t * 64;
    #pragma unroll
    for (int r = 0; r < 13; r++) {
        int nn = ty + 16 * r;
        if (nn >= 200) continue;   // uniform across each 16-lane group
        float s = g[r][0] + g[r][1] + g[r][2] + g[r][3];
        #pragma unroll
        for (int o = 8; o > 0; o >>= 1) s += __shfl_xor_sync(0xffffffffu, s, o, 16);
        float mean = s * (1.f / 64.f);
        float vv = 0.f;
        #pragma unroll
        for (int c = 0; c < 4; c++) { float dg = g[r][c] - mean; vv += dg * dg; }
        #pragma unroll
        for (int o = 8; o > 0; o >>= 1) vv += __shfl_xor_sync(0xffffffffu, vv, o, 16);
        float rstd = rsqrtf(vv * (1.f / 64.f) + 1e-5f);
        #pragma unroll
        for (int c = 0; c < 4; c++) {
            int j = tx + 16 * c;
            float hv = hbase[(long)nn * 3072 + j];
            obase[(long)nn * 3072 + j] =
                hv + (g[r][c] - mean) * rstd * __ldg(g1 + j) + __ldg(beta1 + j);
        }
    }
}

// ---------------------------------------------------------------------------
extern "C" void kernel_launch(void* const* d_in, const int* in_sizes, int n_in,
                              void* d_out, int out_size)
{
    const float* x     = (const float*)d_in[0];
    const float* adj   = (const float*)d_in[1];
    const float* Wq    = (const float*)d_in[2];
    const float* bq    = (const float*)d_in[3];
    const float* Wk    = (const float*)d_in[4];
    const float* bk    = (const float*)d_in[5];
    const float* W1    = (const float*)d_in[6];
    const float* b1    = (const float*)d_in[7];
    const float* W2    = (const float*)d_in[8];
    const float* b2    = (const float*)d_in[9];
    const float* Theta = (const float*)d_in[10];
    const float* g0    = (const float*)d_in[11];
    const float* beta0 = (const float*)d_in[12];
    const float* g1    = (const float*)d_in[13];
    const float* beta1 = (const float*)d_in[14];
    float* out = (float*)d_out;

    const int SMEM_T = 27952 * 4;   // 111808 B
    const int SMEM_S = 27200 * 4;   // 108800 B
    cudaFuncSetAttribute(temporal_kernel,
                         cudaFuncAttributeMaxDynamicSharedMemorySize, SMEM_T);
    cudaFuncSetAttribute(spatial_kernel,
                         cudaFuncAttributeMaxDynamicSharedMemorySize, SMEM_S);

    temporal_kernel<<<dim3(NN, NB), 256, SMEM_T>>>(
        x, Wq, bq, Wk, bk, W1, b1, W2, b2, g0, beta0);
    spatial_kernel<<<dim3(NT, NB), 256, SMEM_S>>>(
        adj, Theta, g1, beta1, out);
}